// round 6
// baseline (speedup 1.0000x reference)
#include <cuda_runtime.h>
#include <cstdint>

#define D         32000
#define D4        (D / 4)            // 8000 float4 per row
#define ROW_BYTES (D * 4)            // 128000 bytes
#define THREADS   1024
#define SEC_THREADS 128              // warps 0-3: secant executors (1 per SMSP)
#define RH        896                // warps 4-31: row holders
#define NV4R      9                  // float4 slots per row-holder (896*9=8064>=8000)
#define NER       36
#define MAX_ITER  100
#define TOL       1e-5f
#define HI_OFFSET 1.9888196601125011f   // -gp(1/32000) = 2 - 2/sqrt(32000)
#define NEG_BIG   -1e30f
#define ROWS      4096
#define ACT_CAP   2048
#define AR_N      16                 // ACT_CAP / SEC_THREADS

__device__ __forceinline__ uint32_t smem_u32(const void* p) {
    uint32_t a;
    asm("{ .reg .u64 t; cvta.to.shared.u64 t, %1; cvt.u32.u64 %0, t; }"
        : "=r"(a) : "l"(p));
    return a;
}

__device__ __forceinline__ void mbar_init(uint32_t mbar, uint32_t count) {
    asm volatile("mbarrier.init.shared.b64 [%0], %1;" :: "r"(mbar), "r"(count) : "memory");
}

__device__ __forceinline__ void tma_prefetch_row(uint32_t dst_smem, const float* src,
                                                 uint32_t mbar) {
    asm volatile("mbarrier.arrive.expect_tx.shared.b64 _, [%0], %1;"
                 :: "r"(mbar), "r"((uint32_t)ROW_BYTES) : "memory");
    asm volatile("cp.async.bulk.shared::cta.global.mbarrier::complete_tx::bytes "
                 "[%0], [%1], %2, [%3];"
                 :: "r"(dst_smem), "l"(src), "r"((uint32_t)ROW_BYTES), "r"(mbar)
                 : "memory");
}

__device__ __forceinline__ void mbar_wait(uint32_t mbar, uint32_t phase) {
    asm volatile(
        "{\n\t"
        ".reg .pred P;\n\t"
        "W%=:\n\t"
        "mbarrier.try_wait.parity.acquire.cta.shared::cta.b64 P, [%0], %1, 0x989680;\n\t"
        "@!P bra W%=;\n\t"
        "}"
        :: "r"(mbar), "r"(phase) : "memory");
}

#define BAR_SEC() asm volatile("bar.sync 1, %0;" :: "n"(SEC_THREADS) : "memory")

__device__ __forceinline__ float warp_sum(float v) {
#pragma unroll
    for (int o = 16; o; o >>= 1) v += __shfl_xor_sync(0xffffffffu, v, o);
    return v;
}

__device__ __forceinline__ float warp_max(float v) {
#pragma unroll
    for (int o = 16; o; o >>= 1) v = fmaxf(v, __shfl_xor_sync(0xffffffffu, v, o));
    return v;
}

__global__ void __launch_bounds__(THREADS, 1)
tsallis_secant_kernel(const float* __restrict__ X, float* __restrict__ Y) {
    extern __shared__ float buf[];          // D floats: TMA staging buffer
    __shared__ float act[ACT_CAP];          // compacted active elements
    __shared__ float red[2][32];            // double-buffered block reduction
    __shared__ float exbuf[2][4];           // secant-warp partial exchange
    __shared__ float2 ex2[4];
    __shared__ int   iscan[32];
    __shared__ int   n_act_s;
    __shared__ float tau_s;
    __shared__ int   fb_s;
    __shared__ __align__(8) uint64_t mbar_storage;

    const int tid  = threadIdx.x;
    const int lane = tid & 31;
    const int wid  = tid >> 5;
    const bool is_sec = (wid < 4);
    const int rh = tid - SEC_THREADS;       // row-holder index, valid if !is_sec

    const uint32_t mbar    = smem_u32(&mbar_storage);
    const uint32_t buf_u32 = smem_u32(buf);

    if (tid == 0) mbar_init(mbar, 1);
    __syncthreads();

    int rb = 0;
    auto block_sum = [&](float s) -> float {   // one-sync block sum
        s = warp_sum(s);
        if (lane == 0) red[rb][wid] = s;
        __syncthreads();
        float t = warp_sum(red[rb][lane]);
        rb ^= 1;
        return t;
    };

    int row = blockIdx.x;
    const int stride = gridDim.x;

    if (tid == 0 && row < ROWS) {
        tma_prefetch_row(buf_u32, X + (size_t)row * D, mbar);
    }
    uint32_t phase = 0;

    for (; row < ROWS; row += stride) {
        mbar_wait(mbar, phase);
        phase ^= 1;

        // ---- row holders: SMEM -> registers + local max ----
        float xv[NER];
        float m = NEG_BIG;
        if (!is_sec) {
            const float4* b4 = reinterpret_cast<const float4*>(buf);
#pragma unroll
            for (int k = 0; k < NV4R; k++) {
                const int i4 = rh + k * RH;
                if (k < NV4R - 1 || i4 < D4) {
                    float4 v = b4[i4];
                    xv[4 * k + 0] = v.x;
                    xv[4 * k + 1] = v.y;
                    xv[4 * k + 2] = v.z;
                    xv[4 * k + 3] = v.w;
                } else {
                    xv[4 * k + 0] = NEG_BIG;
                    xv[4 * k + 1] = NEG_BIG;
                    xv[4 * k + 2] = NEG_BIG;
                    xv[4 * k + 3] = NEG_BIG;
                }
            }
#pragma unroll
            for (int k = 0; k < NER; k++) m = fmaxf(m, xv[k]);
        }
        __syncthreads();   // buf consumed

        const int nrow = row + stride;
        if (tid == 0 && nrow < ROWS) {
            tma_prefetch_row(buf_u32, X + (size_t)nrow * D, mbar);
        }

        // ---- block max ----
        m = warp_max(m);
        if (lane == 0) red[rb][wid] = m;
        __syncthreads();
        const float max_val = warp_max(red[rb][lane]);
        rb ^= 1;

        // ---- deterministic block-scan compaction of {x > max-2} ----
        const float thr = max_val - 2.0f;
        int cnt = 0;
        if (!is_sec) {
#pragma unroll
            for (int k = 0; k < NER; k++) cnt += (xv[k] > thr) ? 1 : 0;
        }
        int inc = cnt;
#pragma unroll
        for (int o = 1; o < 32; o <<= 1) {
            int n = __shfl_up_sync(0xffffffffu, inc, o);
            if (lane >= o) inc += n;
        }
        if (lane == 31) iscan[wid] = inc;
        __syncthreads();
        if (wid == 0) {
            int v = iscan[lane];
            int iv = v;
#pragma unroll
            for (int o = 1; o < 32; o <<= 1) {
                int n = __shfl_up_sync(0xffffffffu, iv, o);
                if (lane >= o) iv += n;
            }
            iscan[lane] = iv - v;
            if (lane == 31) n_act_s = iv;
        }
        __syncthreads();
        if (!is_sec) {
            int pos = iscan[wid] + (inc - cnt);
#pragma unroll
            for (int k = 0; k < NER; k++) {
                if (xv[k] > thr) {
                    if (pos < ACT_CAP) act[pos] = xv[k];
                    pos++;
                }
            }
        }
        __syncthreads();
        const int n_act = n_act_s;

        const float lo0 = max_val;                 // gp(1.0) = 0
        const float hi0 = max_val + HI_OFFSET;

        // ---- secant: warps 0-3, register-resident disjoint quarters ----
        if (is_sec) {
            int fb = (n_act > ACT_CAP) ? 1 : 0;
            float hi = hi0;
            if (!fb) {
                float ar[AR_N];
#pragma unroll
                for (int j = 0; j < AR_N; j++) {
                    const int i = j * SEC_THREADS + tid;
                    ar[j] = (i < n_act) ? act[i] : NEG_BIG;
                }
                // fused dual initial eval (lo0, hi0 >= max_val: identity exact)
                const float cl = fmaf(lo0, -0.5f, 1.0f);
                const float ch = fmaf(hi0, -0.5f, 1.0f);
                float a = 0.0f, b = 0.0f;
#pragma unroll
                for (int j = 0; j < AR_N; j++) {
                    float v = fmaxf(fmaf(ar[j], 0.5f, cl), 0.0f);
                    float w = fmaxf(fmaf(ar[j], 0.5f, ch), 0.0f);
                    a = fmaf(v, v, a);
                    b = fmaf(w, w, b);
                }
                a = warp_sum(a);
                b = warp_sum(b);
                if (lane == 0) ex2[wid] = make_float2(a, b);
                BAR_SEC();
                float f_lo = ((ex2[0].x + ex2[1].x) + (ex2[2].x + ex2[3].x)) - 1.0f;
                float f_hi = ((ex2[0].y + ex2[1].y) + (ex2[2].y + ex2[3].y)) - 1.0f;
                float lo = lo0;
                int eb = 0;

#pragma unroll 1
                for (int it = 0; it < MAX_ITER; it++) {
                    const float diff = f_lo - f_hi;
                    if (diff * diff < TOL) break;
                    const float tau = (lo * f_hi - hi * f_lo) / (f_hi - f_lo);
                    if (!(tau >= max_val)) { fb = 1; break; }  // overshoot / NaN
                    lo = hi;
                    f_lo = f_hi;
                    hi = tau;
                    const float c2 = fmaf(tau, -0.5f, 1.0f);
                    float s = 0.0f;
#pragma unroll
                    for (int j = 0; j < AR_N; j++) {
                        float v = fmaxf(fmaf(ar[j], 0.5f, c2), 0.0f);
                        s = fmaf(v, v, s);
                    }
                    s = warp_sum(s);
                    if (lane == 0) exbuf[eb][wid] = s;
                    BAR_SEC();
                    f_hi = ((exbuf[eb][0] + exbuf[eb][1]) +
                            (exbuf[eb][2] + exbuf[eb][3])) - 1.0f;
                    eb ^= 1;
                }
            }
            if (wid == 0 && lane == 0) { tau_s = hi; fb_s = fb; }
        }
        __syncthreads();

        float tau_final;
        if (fb_s) {
            // ---- rare exact fallback: block-wide secant over full row ----
            auto part_full = [&](float c2) -> float {
                if (is_sec) return 0.0f;
                float a0 = 0.f, a1 = 0.f, a2 = 0.f, a3 = 0.f;
#pragma unroll
                for (int k = 0; k < NER; k += 4) {
                    float v0 = fmaxf(fmaf(xv[k + 0], 0.5f, c2), 0.0f);
                    float v1 = fmaxf(fmaf(xv[k + 1], 0.5f, c2), 0.0f);
                    float v2 = fmaxf(fmaf(xv[k + 2], 0.5f, c2), 0.0f);
                    float v3 = fmaxf(fmaf(xv[k + 3], 0.5f, c2), 0.0f);
                    a0 = fmaf(v0, v0, a0);
                    a1 = fmaf(v1, v1, a1);
                    a2 = fmaf(v2, v2, a2);
                    a3 = fmaf(v3, v3, a3);
                }
                return (a0 + a1) + (a2 + a3);
            };
            float lo = lo0, hi = hi0;
            float f_lo = block_sum(part_full(fmaf(lo, -0.5f, 1.0f))) - 1.0f;
            float f_hi = block_sum(part_full(fmaf(hi, -0.5f, 1.0f))) - 1.0f;
#pragma unroll 1
            for (int it = 0; it < MAX_ITER; it++) {
                const float diff = f_lo - f_hi;
                if (diff * diff < TOL) break;
                const float tau = (lo * f_hi - hi * f_lo) / (f_hi - f_lo);
                lo = hi;
                f_lo = f_hi;
                hi = tau;
                f_hi = block_sum(part_full(fmaf(tau, -0.5f, 1.0f))) - 1.0f;
            }
            tau_final = hi;
        } else {
            tau_final = tau_s;
        }

        // ---- row holders write p(X - tau_final) ----
        if (!is_sec) {
            float4* y4 = reinterpret_cast<float4*>(Y) + (size_t)row * D4;
            const float c2 = fmaf(tau_final, -0.5f, 1.0f);
#pragma unroll
            for (int k = 0; k < NV4R; k++) {
                const int i4 = rh + k * RH;
                if (k < NV4R - 1 || i4 < D4) {
                    float v0 = fmaxf(fmaf(xv[4 * k + 0], 0.5f, c2), 0.0f);
                    float v1 = fmaxf(fmaf(xv[4 * k + 1], 0.5f, c2), 0.0f);
                    float v2 = fmaxf(fmaf(xv[4 * k + 2], 0.5f, c2), 0.0f);
                    float v3 = fmaxf(fmaf(xv[4 * k + 3], 0.5f, c2), 0.0f);
                    float4 r;
                    r.x = v0 * v0;
                    r.y = v1 * v1;
                    r.z = v2 * v2;
                    r.w = v3 * v3;
                    __stcs(&y4[i4], r);
                }
            }
        }
        __syncthreads();   // shared-state reuse fence before next row
    }
}

extern "C" void kernel_launch(void* const* d_in, const int* in_sizes, int n_in,
                              void* d_out, int out_size) {
    const float* X = (const float*)d_in[0];
    float* Y = (float*)d_out;

    static int n_sm = 0;
    if (n_sm == 0) {
        cudaDeviceGetAttribute(&n_sm, cudaDevAttrMultiProcessorCount, 0);
        cudaFuncSetAttribute(tsallis_secant_kernel,
                             cudaFuncAttributeMaxDynamicSharedMemorySize,
                             ROW_BYTES);
    }
    tsallis_secant_kernel<<<n_sm, THREADS, ROW_BYTES>>>(X, Y);
}

// round 7
// speedup vs baseline: 1.2012x; 1.2012x over previous
#include <cuda_runtime.h>
#include <cstdint>

#define D         32000
#define D4        (D / 4)            // 8000 float4 per row
#define ROW_BYTES (D * 4)            // 128000 bytes
#define THREADS   1024
#define NV4       8
#define NE        32
#define MAX_ITER  100
#define TOL       1e-5f
#define HI_OFFSET 1.9888196601125011f   // -gp(1/32000) = 2 - 2/sqrt(32000)
#define NEG_BIG   -1e30f
#define ROWS      4096

__device__ __forceinline__ uint32_t smem_u32(const void* p) {
    uint32_t a;
    asm("{ .reg .u64 t; cvta.to.shared.u64 t, %1; cvt.u32.u64 %0, t; }"
        : "=r"(a) : "l"(p));
    return a;
}

__device__ __forceinline__ void mbar_init(uint32_t mbar, uint32_t count) {
    asm volatile("mbarrier.init.shared.b64 [%0], %1;" :: "r"(mbar), "r"(count) : "memory");
}

__device__ __forceinline__ void tma_prefetch_row(uint32_t dst_smem, const float* src,
                                                 uint32_t mbar) {
    asm volatile("mbarrier.arrive.expect_tx.shared.b64 _, [%0], %1;"
                 :: "r"(mbar), "r"((uint32_t)ROW_BYTES) : "memory");
    asm volatile("cp.async.bulk.shared::cta.global.mbarrier::complete_tx::bytes "
                 "[%0], [%1], %2, [%3];"
                 :: "r"(dst_smem), "l"(src), "r"((uint32_t)ROW_BYTES), "r"(mbar)
                 : "memory");
}

__device__ __forceinline__ void mbar_wait(uint32_t mbar, uint32_t phase) {
    asm volatile(
        "{\n\t"
        ".reg .pred P;\n\t"
        "W%=:\n\t"
        "mbarrier.try_wait.parity.acquire.cta.shared::cta.b64 P, [%0], %1, 0x989680;\n\t"
        "@!P bra W%=;\n\t"
        "}"
        :: "r"(mbar), "r"(phase) : "memory");
}

__device__ __forceinline__ float warp_sum(float v) {
#pragma unroll
    for (int o = 16; o; o >>= 1) v += __shfl_xor_sync(0xffffffffu, v, o);
    return v;
}

__device__ __forceinline__ float warp_max(float v) {
#pragma unroll
    for (int o = 16; o; o >>= 1) v = fmaxf(v, __shfl_xor_sync(0xffffffffu, v, o));
    return v;
}

__global__ void __launch_bounds__(THREADS, 1)
tsallis_secant_kernel(const float* __restrict__ X, float* __restrict__ Y) {
    extern __shared__ float buf[];          // D floats: TMA staging buffer
    __shared__ float red[2][32];            // double-buffered reduction scratch
    __shared__ float2 red2[32];
    __shared__ __align__(8) uint64_t mbar_storage;

    const int tid  = threadIdx.x;
    const int lane = tid & 31;
    const int wid  = tid >> 5;

    const uint32_t mbar    = smem_u32(&mbar_storage);
    const uint32_t buf_u32 = smem_u32(buf);

    if (tid == 0) mbar_init(mbar, 1);
    __syncthreads();

    int rb = 0;  // reduction buffer toggle (uniform across threads)

    auto block_sum = [&](float s) -> float {   // one-sync block sum
        s = warp_sum(s);
        if (lane == 0) red[rb][wid] = s;
        __syncthreads();
        float t = warp_sum(red[rb][lane]);
        rb ^= 1;
        return t;
    };

    int row = blockIdx.x;
    const int stride = gridDim.x;

    if (tid == 0 && row < ROWS) {
        tma_prefetch_row(buf_u32, X + (size_t)row * D, mbar);
    }
    uint32_t phase = 0;

    for (; row < ROWS; row += stride) {
        mbar_wait(mbar, phase);
        phase ^= 1;

        // ---- SMEM -> registers, fused local max ----
        float xv[NE];
        float m = NEG_BIG;
        const float4* b4 = reinterpret_cast<const float4*>(buf);
#pragma unroll
        for (int k = 0; k < NV4; k++) {
            const int i4 = tid + k * THREADS;
            if (k < NV4 - 1 || i4 < D4) {
                float4 v = b4[i4];
                xv[4 * k + 0] = v.x;
                xv[4 * k + 1] = v.y;
                xv[4 * k + 2] = v.z;
                xv[4 * k + 3] = v.w;
            } else {
                xv[4 * k + 0] = NEG_BIG;
                xv[4 * k + 1] = NEG_BIG;
                xv[4 * k + 2] = NEG_BIG;
                xv[4 * k + 3] = NEG_BIG;
            }
        }
#pragma unroll
        for (int k = 0; k < NE; k++) m = fmaxf(m, xv[k]);

        __syncthreads();   // all threads done reading buf

        // ---- kick prefetch of next row (overlaps everything below) ----
        const int nrow = row + stride;
        if (tid == 0 && nrow < ROWS) {
            tma_prefetch_row(buf_u32, X + (size_t)nrow * D, mbar);
        }

        // ---- block max (one-sync) ----
        m = warp_max(m);
        if (lane == 0) red[rb][wid] = m;
        __syncthreads();
        const float max_val = warp_max(red[rb][lane]);
        rb ^= 1;

        // ---- per-thread register pack of active set {x > max-2} + mask ----
        const float thr = max_val - 2.0f;
        float pk0 = NEG_BIG, pk1 = NEG_BIG, pk2 = NEG_BIG, pk3 = NEG_BIG;
        int c = 0;
        unsigned amask = 0;                 // bit k: float4 slot k has an active
#pragma unroll
        for (int k = 0; k < NE; k++) {
            float x = xv[k];
            if (x > thr) {
                if      (c == 0) pk0 = x;
                else if (c == 1) pk1 = x;
                else if (c == 2) pk2 = x;
                else if (c == 3) pk3 = x;
                c++;
                amask |= 1u << (k >> 2);
            }
        }
        const bool full = (c > 4);          // rare per-thread fallback

        // ---- zero-prefill: stores of all-inactive float4s start NOW ----
        // (exact: for tau >= max_val those outputs are exactly 0; fast path
        //  guarantees tau >= max_val, fallback path overwrites everything)
        float4* y4 = reinterpret_cast<float4*>(Y) + (size_t)row * D4;
        {
            const float4 z4 = make_float4(0.f, 0.f, 0.f, 0.f);
#pragma unroll
            for (int k = 0; k < NV4; k++) {
                const int i4 = tid + k * THREADS;
                if ((k < NV4 - 1 || i4 < D4) && !((amask >> k) & 1u)) {
                    __stcs(&y4[i4], z4);
                }
            }
        }

        // full-row partial sum for one tau (this thread's 32 elements)
        auto part_full = [&](float c2) -> float {
            float a0 = 0.f, a1 = 0.f, a2 = 0.f, a3 = 0.f;
#pragma unroll
            for (int k = 0; k < NE; k += 4) {
                float v0 = fmaxf(fmaf(xv[k + 0], 0.5f, c2), 0.0f);
                float v1 = fmaxf(fmaf(xv[k + 1], 0.5f, c2), 0.0f);
                float v2 = fmaxf(fmaf(xv[k + 2], 0.5f, c2), 0.0f);
                float v3 = fmaxf(fmaf(xv[k + 3], 0.5f, c2), 0.0f);
                a0 = fmaf(v0, v0, a0);
                a1 = fmaf(v1, v1, a1);
                a2 = fmaf(v2, v2, a2);
                a3 = fmaf(v3, v3, a3);
            }
            return (a0 + a1) + (a2 + a3);
        };

        // packed partial (valid when tau >= max_val and !full)
        auto part_packed = [&](float c2) -> float {
            float v0 = fmaxf(fmaf(pk0, 0.5f, c2), 0.0f);
            float v1 = fmaxf(fmaf(pk1, 0.5f, c2), 0.0f);
            float v2 = fmaxf(fmaf(pk2, 0.5f, c2), 0.0f);
            float v3 = fmaxf(fmaf(pk3, 0.5f, c2), 0.0f);
            return fmaf(v0, v0, fmaf(v1, v1, fmaf(v2, v2, v3 * v3)));
        };

        // exact f(tau) for ANY tau (uniform branch on tau)
        auto eval = [&](float tau) -> float {
            const float c2 = fmaf(tau, -0.5f, 1.0f);
            float a;
            if (tau >= max_val) a = full ? part_full(c2) : part_packed(c2);
            else                a = part_full(c2);
            return block_sum(a);
        };

        // ---- fused initial evals (both taus >= max_val by construction) ----
        float lo = max_val;                 // gp(1.0) = 0
        float hi = max_val + HI_OFFSET;
        float f_lo, f_hi;
        {
            const float cl = fmaf(lo, -0.5f, 1.0f);
            const float ch = fmaf(hi, -0.5f, 1.0f);
            float a, b;
            if (full) { a = part_full(cl); b = part_full(ch); }
            else      { a = part_packed(cl); b = part_packed(ch); }
            a = warp_sum(a);
            b = warp_sum(b);
            if (lane == 0) red2[wid] = make_float2(a, b);
            __syncthreads();
            float2 t = red2[lane];
            f_lo = warp_sum(t.x) - 1.0f;
            f_hi = warp_sum(t.y) - 1.0f;
        }

        // ---- secant with early exit + left-overshoot tracking ----
        bool left = false;                  // did any iterate go below max_val?
#pragma unroll 1
        for (int it = 0; it < MAX_ITER; it++) {
            const float diff = f_lo - f_hi;
            if (diff * diff < TOL) break;
            const float tau = (lo * f_hi - hi * f_lo) / (f_hi - f_lo);
            if (!(tau >= max_val)) left = true;   // uniform (tau uniform)
            lo = hi;
            f_lo = f_hi;
            hi = tau;
            f_hi = eval(hi) - 1.0f;
        }
        const float tau_final = hi;

        // ---- final store ----
        const float c2 = fmaf(tau_final, -0.5f, 1.0f);
        if (!left && tau_final >= max_val) {
            // fast path: only float4s containing actives (rest already 0)
#pragma unroll
            for (int k = 0; k < NV4; k++) {
                const int i4 = tid + k * THREADS;
                if ((amask >> k) & 1u) {
                    if (k < NV4 - 1 || i4 < D4) {
                        float v0 = fmaxf(fmaf(xv[4 * k + 0], 0.5f, c2), 0.0f);
                        float v1 = fmaxf(fmaf(xv[4 * k + 1], 0.5f, c2), 0.0f);
                        float v2 = fmaxf(fmaf(xv[4 * k + 2], 0.5f, c2), 0.0f);
                        float v3 = fmaxf(fmaf(xv[4 * k + 3], 0.5f, c2), 0.0f);
                        float4 r;
                        r.x = v0 * v0;
                        r.y = v1 * v1;
                        r.z = v2 * v2;
                        r.w = v3 * v3;
                        __stcs(&y4[i4], r);
                    }
                }
            }
        } else {
            // rare: tau dipped below max at some point — overwrite everything
            // (same thread owns same addresses as its prefill: ordered)
#pragma unroll
            for (int k = 0; k < NV4; k++) {
                const int i4 = tid + k * THREADS;
                if (k < NV4 - 1 || i4 < D4) {
                    float v0 = fmaxf(fmaf(xv[4 * k + 0], 0.5f, c2), 0.0f);
                    float v1 = fmaxf(fmaf(xv[4 * k + 1], 0.5f, c2), 0.0f);
                    float v2 = fmaxf(fmaf(xv[4 * k + 2], 0.5f, c2), 0.0f);
                    float v3 = fmaxf(fmaf(xv[4 * k + 3], 0.5f, c2), 0.0f);
                    float4 r;
                    r.x = v0 * v0;
                    r.y = v1 * v1;
                    r.z = v2 * v2;
                    r.w = v3 * v3;
                    __stcs(&y4[i4], r);
                }
            }
        }
        __syncthreads();   // red/red2 reuse fence before next row
    }
}

extern "C" void kernel_launch(void* const* d_in, const int* in_sizes, int n_in,
                              void* d_out, int out_size) {
    const float* X = (const float*)d_in[0];
    float* Y = (float*)d_out;

    static int n_sm = 0;
    if (n_sm == 0) {
        cudaDeviceGetAttribute(&n_sm, cudaDevAttrMultiProcessorCount, 0);
        cudaFuncSetAttribute(tsallis_secant_kernel,
                             cudaFuncAttributeMaxDynamicSharedMemorySize,
                             ROW_BYTES);
    }
    tsallis_secant_kernel<<<n_sm, THREADS, ROW_BYTES>>>(X, Y);
}